// round 12
// baseline (speedup 1.0000x reference)
#include <cuda_runtime.h>

// Scratch (problem-sized per spec):
//   g_sum   : per-torus-node accumulator {sum_x, sum_y, sum_z, count}
//   g_stage : per-torus-node {x, y, z, precomputed_dst_gate_term a_d}
//   g_first : per-terrain-node packed (e<<34 | op<<32 | polarity_bits), min-by-e
__device__ float4             g_sum[1000000];
__device__ float4             g_stage[1000000];
__device__ unsigned long long g_first[2000000];

// ---------------------------------------------------------------------------
// Stage 1: fused init, high-MLP — each thread: 2 terrain nodes + 1 torus node.
//  terrain i0,i0+1: out_t = x_terrain; g_first = MAX (one 16B store)
//  torus j:         g_sum = 0; g_stage = {x_tor, a = gate_W[0:3]·x_tor + b}
// Thread count = max(ceil(n_t/2), n_tor).
// ---------------------------------------------------------------------------
__global__ void k_init_all(const float4* __restrict__ x_terrain4,
                           float4* __restrict__ out_t4,
                           const float* __restrict__ x_tor,
                           const float* __restrict__ gate_W,
                           const float* __restrict__ gate_b,
                           int n_t, int n_tor) {
    int i = blockIdx.x * blockDim.x + threadIdx.x;

    int i0 = 2 * i;
    if (i0 + 1 < n_t) {
        float4 xa = x_terrain4[i0];
        float4 xb = x_terrain4[i0 + 1];
        out_t4[i0]     = xa;
        out_t4[i0 + 1] = xb;
        ulonglong2 ff; ff.x = ~0ull; ff.y = ~0ull;
        *reinterpret_cast<ulonglong2*>(&g_first[i0]) = ff;
    } else if (i0 < n_t) {
        out_t4[i0] = x_terrain4[i0];
        g_first[i0] = ~0ull;
    }

    if (i < n_tor) {
        float x0 = x_tor[3 * i + 0];
        float x1 = x_tor[3 * i + 1];
        float x2 = x_tor[3 * i + 2];
        g_sum[i] = make_float4(0.f, 0.f, 0.f, 0.f);
        float a = __ldg(&gate_W[0]) * x0 + __ldg(&gate_W[1]) * x1
                + __ldg(&gate_W[2]) * x2 + __ldg(&gate_b[0]);
        g_stage[i] = make_float4(x0, x1, x2, a);
    }
}

// ---------------------------------------------------------------------------
// Stage 2a (s2): seq-conv scatter + packed assignment segment-min.
// 4 edges/thread; index/attr streams coalesced vector loads.
// Scattered ops/edge: gather x[s], RED.128 out_t[d], ATOM.64 g_first[a] = 3.
// ---------------------------------------------------------------------------
__global__ void k_edges_seq(const int* __restrict__ seq_src,
                            const int* __restrict__ seq_dst,
                            const int* __restrict__ assign_src,
                            const int* __restrict__ assign_dst,
                            const float* __restrict__ polarity,
                            const float4* __restrict__ x_terrain4,
                            const float* __restrict__ W_seq,
                            float4* __restrict__ out_t4,
                            int e_seq) {
    int t = blockIdx.x * blockDim.x + threadIdx.x;
    int e0 = 4 * t;
    if (e0 >= e_seq) return;

    float w[16];
#pragma unroll
    for (int j = 0; j < 16; ++j) w[j] = __ldg(&W_seq[j]);

    if (e0 + 3 < e_seq) {
        int4   s4 = __ldg((const int4*)(seq_src) + t);
        int4   d4 = __ldg((const int4*)(seq_dst) + t);
        int4   a4 = __ldg((const int4*)(assign_src) + t);
        int4   o4 = __ldg((const int4*)(assign_dst) + t);
        float4 p4 = __ldg((const float4*)(polarity) + t);
        int ss[4] = {s4.x, s4.y, s4.z, s4.w};
        int dd[4] = {d4.x, d4.y, d4.z, d4.w};
        int aa[4] = {a4.x, a4.y, a4.z, a4.w};
        int oo[4] = {o4.x, o4.y, o4.z, o4.w};
        float pp[4] = {p4.x, p4.y, p4.z, p4.w};
#pragma unroll
        for (int k = 0; k < 4; ++k) {
            unsigned long long op = (unsigned long long)(max(0, min(oo[k], 3)));
            unsigned long long packed = ((unsigned long long)(e0 + k) << 34)
                                      | (op << 32)
                                      | (unsigned long long)__float_as_uint(pp[k]);
            atomicMin(&g_first[aa[k]], packed);

            float4 x = __ldg(&x_terrain4[ss[k]]);
            float m0 = w[0]  * x.x + w[1]  * x.y + w[2]  * x.z + w[3]  * x.w;
            float m1 = w[4]  * x.x + w[5]  * x.y + w[6]  * x.z + w[7]  * x.w;
            float m2 = w[8]  * x.x + w[9]  * x.y + w[10] * x.z + w[11] * x.w;
            float m3 = w[12] * x.x + w[13] * x.y + w[14] * x.z + w[15] * x.w;
            float4* dst = &out_t4[dd[k]];
            asm volatile("red.global.add.v4.f32 [%0], {%1, %2, %3, %4};"
                         :: "l"(dst), "f"(m0), "f"(m1), "f"(m2), "f"(m3) : "memory");
        }
    } else {
        for (int e = e0; e < e_seq; ++e) {
            int s = seq_src[e];
            int d = seq_dst[e];
            int a = assign_src[e];
            unsigned long long op = (unsigned long long)(max(0, min(assign_dst[e], 3)));
            unsigned long long packed = ((unsigned long long)e << 34)
                                      | (op << 32)
                                      | (unsigned long long)__float_as_uint(polarity[e]);
            atomicMin(&g_first[a], packed);

            float4 x = __ldg(&x_terrain4[s]);
            float m0 = w[0]  * x.x + w[1]  * x.y + w[2]  * x.z + w[3]  * x.w;
            float m1 = w[4]  * x.x + w[5]  * x.y + w[6]  * x.z + w[7]  * x.w;
            float m2 = w[8]  * x.x + w[9]  * x.y + w[10] * x.z + w[11] * x.w;
            float m3 = w[12] * x.x + w[13] * x.y + w[14] * x.z + w[15] * x.w;
            float4* dst = &out_t4[d];
            asm volatile("red.global.add.v4.f32 [%0], {%1, %2, %3, %4};"
                         :: "l"(dst), "f"(m0), "f"(m1), "f"(m2), "f"(m3) : "memory");
        }
    }
}

// ---------------------------------------------------------------------------
// Stage 2b (s0): transport edges, 4 edges/thread.
// Scattered ops/edge: LDG.128 stage[src], LDG.32 stage[dst].w, RED.128 = 3.
// Runs at the L1tex wavefront ceiling (~1 wf/cyc/SM) — structural floor.
// ---------------------------------------------------------------------------
__global__ void k_transport(const int* __restrict__ tr_src,
                            const int* __restrict__ tr_dst,
                            const float* __restrict__ gate_W,
                            int e_tr) {
    int t = blockIdx.x * blockDim.x + threadIdx.x;
    int e0 = 4 * t;
    if (e0 >= e_tr) return;

    float w3 = __ldg(&gate_W[3]);
    float w4 = __ldg(&gate_W[4]);
    float w5 = __ldg(&gate_W[5]);
    const float* stage_f = (const float*)g_stage;

    if (e0 + 3 < e_tr) {
        int4 s4 = __ldg((const int4*)(tr_src) + t);
        int4 d4 = __ldg((const int4*)(tr_dst) + t);
        int ss[4] = {s4.x, s4.y, s4.z, s4.w};
        int dd[4] = {d4.x, d4.y, d4.z, d4.w};
#pragma unroll
        for (int k = 0; k < 4; ++k) {
            float4 v = __ldg(&g_stage[ss[k]]);
            float a  = __ldg(&stage_f[4 * dd[k] + 3]);
            float z  = a + w3 * v.x + w4 * v.y + w5 * v.z;
            float g  = 1.0f / (1.0f + __expf(-z));
            float4* dst = &g_sum[dd[k]];
            asm volatile("red.global.add.v4.f32 [%0], {%1, %2, %3, %4};"
                         :: "l"(dst), "f"(g * v.x), "f"(g * v.y), "f"(g * v.z), "f"(1.0f)
                         : "memory");
        }
    } else {
        for (int e = e0; e < e_tr; ++e) {
            int s = tr_src[e];
            int d = tr_dst[e];
            float4 v = __ldg(&g_stage[s]);
            float a  = __ldg(&stage_f[4 * d + 3]);
            float z  = a + w3 * v.x + w4 * v.y + w5 * v.z;
            float g  = 1.0f / (1.0f + __expf(-z));
            float4* dst = &g_sum[d];
            asm volatile("red.global.add.v4.f32 [%0], {%1, %2, %3, %4};"
                         :: "l"(dst), "f"(g * v.x), "f"(g * v.y), "f"(g * v.z), "f"(1.0f)
                         : "memory");
        }
    }
}

// ---------------------------------------------------------------------------
// Stage 3: fused post, high-MLP — each thread: 2 terrain nodes + 1 torus node.
//  terrain: operator transform (decodes packed min — fully coalesced)
//  torus:   out = x + sum / max(count, 1)
// ---------------------------------------------------------------------------
__global__ void k_post(float4* __restrict__ out_t4,
                       const float* __restrict__ op_W,
                       const float* __restrict__ op_b,
                       float* __restrict__ out_tor,
                       int n_t, int e_as, int n_tor) {
    int i = blockIdx.x * blockDim.x + threadIdx.x;

    int i0 = 2 * i;
    if (i0 < n_t) {
        int cnt = (i0 + 1 < n_t) ? 2 : 1;
        ulonglong2 vv;
        if (cnt == 2) {
            vv = *reinterpret_cast<const ulonglong2*>(&g_first[i0]);
        } else {
            vv.x = g_first[i0]; vv.y = ~0ull;
        }
#pragma unroll
        for (int k = 0; k < 2; ++k) {
            if (k >= cnt) break;
            unsigned long long v = (k == 0) ? vv.x : vv.y;
            unsigned int f = (unsigned int)(v >> 34);
            if (f >= (unsigned int)e_as) continue;

            int   op = (int)((v >> 32) & 3ull);
            float p  = __uint_as_float((unsigned int)(v & 0xffffffffull));

            float4 x = out_t4[i0 + k];
            const float* W = op_W + op * 20;   // [4][5] row-major
            const float* b = op_b + op * 4;

            float4 y;
            y.x = __ldg(&W[0])  * x.x + __ldg(&W[1])  * x.y + __ldg(&W[2])  * x.z + __ldg(&W[3])  * x.w + __ldg(&W[4])  * p + __ldg(&b[0]);
            y.y = __ldg(&W[5])  * x.x + __ldg(&W[6])  * x.y + __ldg(&W[7])  * x.z + __ldg(&W[8])  * x.w + __ldg(&W[9])  * p + __ldg(&b[1]);
            y.z = __ldg(&W[10]) * x.x + __ldg(&W[11]) * x.y + __ldg(&W[12]) * x.z + __ldg(&W[13]) * x.w + __ldg(&W[14]) * p + __ldg(&b[2]);
            y.w = __ldg(&W[15]) * x.x + __ldg(&W[16]) * x.y + __ldg(&W[17]) * x.z + __ldg(&W[18]) * x.w + __ldg(&W[19]) * p + __ldg(&b[3]);
            out_t4[i0 + k] = y;
        }
    }

    if (i < n_tor) {
        float4 sv = g_sum[i];
        float4 xv = g_stage[i];
        float inv = 1.0f / fmaxf(sv.w, 1.0f);
        out_tor[3 * i + 0] = xv.x + sv.x * inv;
        out_tor[3 * i + 1] = xv.y + sv.y * inv;
        out_tor[3 * i + 2] = xv.z + sv.z * inv;
    }
}

extern "C" void kernel_launch(void* const* d_in, const int* in_sizes, int n_in,
                              void* d_out, int out_size) {
    const float* x_terrain  = (const float*)d_in[0];
    const float* polarity   = (const float*)d_in[1];
    const float* x_torus    = (const float*)d_in[2];
    const int*   seq_ei     = (const int*)d_in[3];
    const int*   assign_src = (const int*)d_in[4];
    const int*   assign_dst = (const int*)d_in[5];
    const int*   tr_ei      = (const int*)d_in[6];
    const float* W_seq      = (const float*)d_in[7];
    const float* op_W       = (const float*)d_in[8];
    const float* op_b       = (const float*)d_in[9];
    const float* gate_W     = (const float*)d_in[10];
    const float* gate_b     = (const float*)d_in[11];

    const int TD = 4, OD = 3;
    int n_t   = in_sizes[0] / TD;      // 2,000,000
    int e_as  = in_sizes[4];           // 2,000,000
    int n_tor = in_sizes[2] / OD;      // 1,000,000
    int e_seq = in_sizes[3] / 2;       // 2,000,000
    int e_tr  = in_sizes[6] / 2;       // 8,000,000

    float* out_t   = (float*)d_out;            // [n_t, 4]
    float* out_tor = out_t + (size_t)n_t * TD; // [n_tor, 3]

    // One-time side-stream + events for fork/join graph branches.
    static cudaStream_t s2 = nullptr;
    static cudaEvent_t evFork = nullptr, evJoin = nullptr;
    if (s2 == nullptr) {
        cudaStreamCreateWithFlags(&s2, cudaStreamNonBlocking);
        cudaEventCreateWithFlags(&evFork, cudaEventDisableTiming);
        cudaEventCreateWithFlags(&evJoin, cudaEventDisableTiming);
    }

    const int B = 256;
    int n_half = (n_t + 1) / 2;                  // threads for 2-nodes-each
    int n_bookend = (n_half > n_tor) ? n_half : n_tor;

    // Stage 1: fused, high-MLP init on origin stream.
    k_init_all<<<(n_bookend + B - 1) / B, B>>>((const float4*)x_terrain, (float4*)out_t,
                                               x_torus, gate_W, gate_b, n_t, n_tor);

    // Fork after init: seq edges on s2, transport on origin stream.
    cudaEventRecord(evFork, 0);
    cudaStreamWaitEvent(s2, evFork, 0);

    int t_seq = (e_seq + 3) / 4;
    k_edges_seq<<<(t_seq + B - 1) / B, B, 0, s2>>>(
        seq_ei, seq_ei + e_seq, assign_src, assign_dst, polarity,
        (const float4*)x_terrain, W_seq, (float4*)out_t, e_seq);

    cudaEventRecord(evJoin, s2);

    int t_tr = (e_tr + 3) / 4;
    k_transport<<<(t_tr + B - 1) / B, B>>>(tr_ei, tr_ei + e_tr, gate_W, e_tr);

    // Join: post kernel needs both edge kernels complete.
    cudaStreamWaitEvent(0, evJoin, 0);

    // Stage 3: fused, high-MLP post (operator transform + torus finalize).
    k_post<<<(n_bookend + B - 1) / B, B>>>((float4*)out_t, op_W, op_b, out_tor,
                                           n_t, e_as, n_tor);
}

// round 13
// speedup vs baseline: 1.4615x; 1.4615x over previous
#include <cuda_runtime.h>

// Scratch (problem-sized per spec):
//   g_sum   : per-torus-node accumulator {sum_x, sum_y, sum_z, count}
//   g_stage : per-torus-node {x, y, z, precomputed_dst_gate_term a_d}
//   g_first : per-terrain-node packed (e<<34 | op<<32 | polarity_bits), min-by-e
__device__ float4             g_sum[1000000];
__device__ float4             g_stage[1000000];
__device__ unsigned long long g_first[2000000];

// ---------------------------------------------------------------------------
// Stage 1: fused init, stride-split high-MLP.
// Thread i handles: terrain node i, terrain node i+n_half, torus node i.
// Every instruction stays fully coalesced across the warp (unit stride).
// ---------------------------------------------------------------------------
__global__ void k_init_all(const float4* __restrict__ x_terrain4,
                           float4* __restrict__ out_t4,
                           const float* __restrict__ x_tor,
                           const float* __restrict__ gate_W,
                           const float* __restrict__ gate_b,
                           int n_t, int n_half, int n_tor) {
    int i = blockIdx.x * blockDim.x + threadIdx.x;

    if (i < n_half) {
        out_t4[i] = x_terrain4[i];
        g_first[i] = ~0ull;
        int j = i + n_half;
        if (j < n_t) {
            out_t4[j] = x_terrain4[j];
            g_first[j] = ~0ull;
        }
    }

    if (i < n_tor) {
        float x0 = x_tor[3 * i + 0];
        float x1 = x_tor[3 * i + 1];
        float x2 = x_tor[3 * i + 2];
        g_sum[i] = make_float4(0.f, 0.f, 0.f, 0.f);
        float a = __ldg(&gate_W[0]) * x0 + __ldg(&gate_W[1]) * x1
                + __ldg(&gate_W[2]) * x2 + __ldg(&gate_b[0]);
        g_stage[i] = make_float4(x0, x1, x2, a);
    }
}

// ---------------------------------------------------------------------------
// Stage 2a (s2): seq-conv scatter + packed assignment segment-min.
// 4 edges/thread; index/attr streams coalesced vector loads.
// Scattered ops/edge: gather x[s], RED.128 out_t[d], ATOM.64 g_first[a] = 3.
// ---------------------------------------------------------------------------
__global__ void k_edges_seq(const int* __restrict__ seq_src,
                            const int* __restrict__ seq_dst,
                            const int* __restrict__ assign_src,
                            const int* __restrict__ assign_dst,
                            const float* __restrict__ polarity,
                            const float4* __restrict__ x_terrain4,
                            const float* __restrict__ W_seq,
                            float4* __restrict__ out_t4,
                            int e_seq) {
    int t = blockIdx.x * blockDim.x + threadIdx.x;
    int e0 = 4 * t;
    if (e0 >= e_seq) return;

    float w[16];
#pragma unroll
    for (int j = 0; j < 16; ++j) w[j] = __ldg(&W_seq[j]);

    if (e0 + 3 < e_seq) {
        int4   s4 = __ldg((const int4*)(seq_src) + t);
        int4   d4 = __ldg((const int4*)(seq_dst) + t);
        int4   a4 = __ldg((const int4*)(assign_src) + t);
        int4   o4 = __ldg((const int4*)(assign_dst) + t);
        float4 p4 = __ldg((const float4*)(polarity) + t);
        int ss[4] = {s4.x, s4.y, s4.z, s4.w};
        int dd[4] = {d4.x, d4.y, d4.z, d4.w};
        int aa[4] = {a4.x, a4.y, a4.z, a4.w};
        int oo[4] = {o4.x, o4.y, o4.z, o4.w};
        float pp[4] = {p4.x, p4.y, p4.z, p4.w};
#pragma unroll
        for (int k = 0; k < 4; ++k) {
            unsigned long long op = (unsigned long long)(max(0, min(oo[k], 3)));
            unsigned long long packed = ((unsigned long long)(e0 + k) << 34)
                                      | (op << 32)
                                      | (unsigned long long)__float_as_uint(pp[k]);
            atomicMin(&g_first[aa[k]], packed);

            float4 x = __ldg(&x_terrain4[ss[k]]);
            float m0 = w[0]  * x.x + w[1]  * x.y + w[2]  * x.z + w[3]  * x.w;
            float m1 = w[4]  * x.x + w[5]  * x.y + w[6]  * x.z + w[7]  * x.w;
            float m2 = w[8]  * x.x + w[9]  * x.y + w[10] * x.z + w[11] * x.w;
            float m3 = w[12] * x.x + w[13] * x.y + w[14] * x.z + w[15] * x.w;
            float4* dst = &out_t4[dd[k]];
            asm volatile("red.global.add.v4.f32 [%0], {%1, %2, %3, %4};"
                         :: "l"(dst), "f"(m0), "f"(m1), "f"(m2), "f"(m3) : "memory");
        }
    } else {
        for (int e = e0; e < e_seq; ++e) {
            int s = seq_src[e];
            int d = seq_dst[e];
            int a = assign_src[e];
            unsigned long long op = (unsigned long long)(max(0, min(assign_dst[e], 3)));
            unsigned long long packed = ((unsigned long long)e << 34)
                                      | (op << 32)
                                      | (unsigned long long)__float_as_uint(polarity[e]);
            atomicMin(&g_first[a], packed);

            float4 x = __ldg(&x_terrain4[s]);
            float m0 = w[0]  * x.x + w[1]  * x.y + w[2]  * x.z + w[3]  * x.w;
            float m1 = w[4]  * x.x + w[5]  * x.y + w[6]  * x.z + w[7]  * x.w;
            float m2 = w[8]  * x.x + w[9]  * x.y + w[10] * x.z + w[11] * x.w;
            float m3 = w[12] * x.x + w[13] * x.y + w[14] * x.z + w[15] * x.w;
            float4* dst = &out_t4[d];
            asm volatile("red.global.add.v4.f32 [%0], {%1, %2, %3, %4};"
                         :: "l"(dst), "f"(m0), "f"(m1), "f"(m2), "f"(m3) : "memory");
        }
    }
}

// ---------------------------------------------------------------------------
// Stage 2b (s0): transport edges, 4 edges/thread.
// Scattered ops/edge: LDG.128 stage[src], LDG.32 stage[dst].w, RED.128 = 3.
// Runs at the L1tex wavefront ceiling (~1 wf/cyc/SM) — structural floor.
// ---------------------------------------------------------------------------
__global__ void k_transport(const int* __restrict__ tr_src,
                            const int* __restrict__ tr_dst,
                            const float* __restrict__ gate_W,
                            int e_tr) {
    int t = blockIdx.x * blockDim.x + threadIdx.x;
    int e0 = 4 * t;
    if (e0 >= e_tr) return;

    float w3 = __ldg(&gate_W[3]);
    float w4 = __ldg(&gate_W[4]);
    float w5 = __ldg(&gate_W[5]);
    const float* stage_f = (const float*)g_stage;

    if (e0 + 3 < e_tr) {
        int4 s4 = __ldg((const int4*)(tr_src) + t);
        int4 d4 = __ldg((const int4*)(tr_dst) + t);
        int ss[4] = {s4.x, s4.y, s4.z, s4.w};
        int dd[4] = {d4.x, d4.y, d4.z, d4.w};
#pragma unroll
        for (int k = 0; k < 4; ++k) {
            float4 v = __ldg(&g_stage[ss[k]]);
            float a  = __ldg(&stage_f[4 * dd[k] + 3]);
            float z  = a + w3 * v.x + w4 * v.y + w5 * v.z;
            float g  = 1.0f / (1.0f + __expf(-z));
            float4* dst = &g_sum[dd[k]];
            asm volatile("red.global.add.v4.f32 [%0], {%1, %2, %3, %4};"
                         :: "l"(dst), "f"(g * v.x), "f"(g * v.y), "f"(g * v.z), "f"(1.0f)
                         : "memory");
        }
    } else {
        for (int e = e0; e < e_tr; ++e) {
            int s = tr_src[e];
            int d = tr_dst[e];
            float4 v = __ldg(&g_stage[s]);
            float a  = __ldg(&stage_f[4 * d + 3]);
            float z  = a + w3 * v.x + w4 * v.y + w5 * v.z;
            float g  = 1.0f / (1.0f + __expf(-z));
            float4* dst = &g_sum[d];
            asm volatile("red.global.add.v4.f32 [%0], {%1, %2, %3, %4};"
                         :: "l"(dst), "f"(g * v.x), "f"(g * v.y), "f"(g * v.z), "f"(1.0f)
                         : "memory");
        }
    }
}

// ---------------------------------------------------------------------------
// Stage 3: fused post, stride-split high-MLP.
// Thread i handles: terrain node i, terrain node i+n_half, torus node i.
// ---------------------------------------------------------------------------
__device__ __forceinline__ void op_transform(float4* __restrict__ out_t4,
                                             const float* __restrict__ op_W,
                                             const float* __restrict__ op_b,
                                             int n, int e_as) {
    unsigned long long v = g_first[n];
    unsigned int f = (unsigned int)(v >> 34);
    if (f >= (unsigned int)e_as) return;

    int   op = (int)((v >> 32) & 3ull);
    float p  = __uint_as_float((unsigned int)(v & 0xffffffffull));

    float4 x = out_t4[n];
    const float* W = op_W + op * 20;   // [4][5] row-major
    const float* b = op_b + op * 4;

    float4 y;
    y.x = __ldg(&W[0])  * x.x + __ldg(&W[1])  * x.y + __ldg(&W[2])  * x.z + __ldg(&W[3])  * x.w + __ldg(&W[4])  * p + __ldg(&b[0]);
    y.y = __ldg(&W[5])  * x.x + __ldg(&W[6])  * x.y + __ldg(&W[7])  * x.z + __ldg(&W[8])  * x.w + __ldg(&W[9])  * p + __ldg(&b[1]);
    y.z = __ldg(&W[10]) * x.x + __ldg(&W[11]) * x.y + __ldg(&W[12]) * x.z + __ldg(&W[13]) * x.w + __ldg(&W[14]) * p + __ldg(&b[2]);
    y.w = __ldg(&W[15]) * x.x + __ldg(&W[16]) * x.y + __ldg(&W[17]) * x.z + __ldg(&W[18]) * x.w + __ldg(&W[19]) * p + __ldg(&b[3]);
    out_t4[n] = y;
}

__global__ void k_post(float4* __restrict__ out_t4,
                       const float* __restrict__ op_W,
                       const float* __restrict__ op_b,
                       float* __restrict__ out_tor,
                       int n_t, int n_half, int e_as, int n_tor) {
    int i = blockIdx.x * blockDim.x + threadIdx.x;

    if (i < n_tor) {
        float4 sv = g_sum[i];
        float4 xv = g_stage[i];
        float inv = 1.0f / fmaxf(sv.w, 1.0f);
        out_tor[3 * i + 0] = xv.x + sv.x * inv;
        out_tor[3 * i + 1] = xv.y + sv.y * inv;
        out_tor[3 * i + 2] = xv.z + sv.z * inv;
    }

    if (i < n_half) {
        op_transform(out_t4, op_W, op_b, i, e_as);
        int j = i + n_half;
        if (j < n_t) op_transform(out_t4, op_W, op_b, j, e_as);
    }
}

extern "C" void kernel_launch(void* const* d_in, const int* in_sizes, int n_in,
                              void* d_out, int out_size) {
    const float* x_terrain  = (const float*)d_in[0];
    const float* polarity   = (const float*)d_in[1];
    const float* x_torus    = (const float*)d_in[2];
    const int*   seq_ei     = (const int*)d_in[3];
    const int*   assign_src = (const int*)d_in[4];
    const int*   assign_dst = (const int*)d_in[5];
    const int*   tr_ei      = (const int*)d_in[6];
    const float* W_seq      = (const float*)d_in[7];
    const float* op_W       = (const float*)d_in[8];
    const float* op_b       = (const float*)d_in[9];
    const float* gate_W     = (const float*)d_in[10];
    const float* gate_b     = (const float*)d_in[11];

    const int TD = 4, OD = 3;
    int n_t   = in_sizes[0] / TD;      // 2,000,000
    int e_as  = in_sizes[4];           // 2,000,000
    int n_tor = in_sizes[2] / OD;      // 1,000,000
    int e_seq = in_sizes[3] / 2;       // 2,000,000
    int e_tr  = in_sizes[6] / 2;       // 8,000,000

    float* out_t   = (float*)d_out;            // [n_t, 4]
    float* out_tor = out_t + (size_t)n_t * TD; // [n_tor, 3]

    // One-time side-stream + events for fork/join graph branches.
    static cudaStream_t s2 = nullptr;
    static cudaEvent_t evFork = nullptr, evJoin = nullptr;
    if (s2 == nullptr) {
        cudaStreamCreateWithFlags(&s2, cudaStreamNonBlocking);
        cudaEventCreateWithFlags(&evFork, cudaEventDisableTiming);
        cudaEventCreateWithFlags(&evJoin, cudaEventDisableTiming);
    }

    const int B = 256;
    int n_half = (n_t + 1) / 2;                     // 1,000,000
    int n_bookend = (n_half > n_tor) ? n_half : n_tor;

    // Stage 1: fused, stride-split init on origin stream.
    k_init_all<<<(n_bookend + B - 1) / B, B>>>((const float4*)x_terrain, (float4*)out_t,
                                               x_torus, gate_W, gate_b,
                                               n_t, n_half, n_tor);

    // Fork after init: seq edges on s2, transport on origin stream.
    cudaEventRecord(evFork, 0);
    cudaStreamWaitEvent(s2, evFork, 0);

    int t_seq = (e_seq + 3) / 4;
    k_edges_seq<<<(t_seq + B - 1) / B, B, 0, s2>>>(
        seq_ei, seq_ei + e_seq, assign_src, assign_dst, polarity,
        (const float4*)x_terrain, W_seq, (float4*)out_t, e_seq);

    cudaEventRecord(evJoin, s2);

    int t_tr = (e_tr + 3) / 4;
    k_transport<<<(t_tr + B - 1) / B, B>>>(tr_ei, tr_ei + e_tr, gate_W, e_tr);

    // Join: post kernel needs both edge kernels complete.
    cudaStreamWaitEvent(0, evJoin, 0);

    // Stage 3: fused, stride-split post (operator transform + torus finalize).
    k_post<<<(n_bookend + B - 1) / B, B>>>((float4*)out_t, op_W, op_b, out_tor,
                                           n_t, n_half, e_as, n_tor);
}

// round 14
// speedup vs baseline: 1.5125x; 1.0349x over previous
#include <cuda_runtime.h>

// Scratch (problem-sized per spec):
//   g_sum   : per-torus-node accumulator {sum_x, sum_y, sum_z, count}
//   g_stage : per-torus-node {x, y, z, precomputed_dst_gate_term a_d}
//   g_first : per-terrain-node packed (e<<34 | op<<32 | polarity_bits), min-by-e
__device__ float4             g_sum[1000000];
__device__ float4             g_stage[1000000];
__device__ unsigned long long g_first[2000000];

// ---------------------------------------------------------------------------
// Stage 1 (s0, serial): fused init — R8's verified-best prologue.
//  terrain: out_t = x_terrain (residual base for RED), g_first = MAX
//  torus:   g_sum = 0; g_stage[n] = {x_tor[n], a_n = gate_W[0:3]·x_tor[n]+b}
// ---------------------------------------------------------------------------
__global__ void k_init_all(const float4* __restrict__ x_terrain4,
                           float4* __restrict__ out_t4,
                           const float* __restrict__ x_tor,
                           const float* __restrict__ gate_W,
                           const float* __restrict__ gate_b,
                           int n_t, int n_tor) {
    int i = blockIdx.x * blockDim.x + threadIdx.x;
    if (i >= n_t) return;
    out_t4[i] = x_terrain4[i];
    g_first[i] = ~0ull;
    if (i < n_tor) {
        g_sum[i] = make_float4(0.f, 0.f, 0.f, 0.f);
        float x0 = x_tor[3 * i + 0];
        float x1 = x_tor[3 * i + 1];
        float x2 = x_tor[3 * i + 2];
        float a = __ldg(&gate_W[0]) * x0 + __ldg(&gate_W[1]) * x1
                + __ldg(&gate_W[2]) * x2 + __ldg(&gate_b[0]);
        g_stage[i] = make_float4(x0, x1, x2, a);
    }
}

// ---------------------------------------------------------------------------
// Stage 2a (s2): seq-conv scatter + packed assignment segment-min.
// 4 edges/thread; index/attr streams coalesced vector loads.
// Scattered ops/edge: gather x[s], RED.128 out_t[d], ATOM.64 g_first[a] = 3.
// ---------------------------------------------------------------------------
__global__ void k_edges_seq(const int* __restrict__ seq_src,
                            const int* __restrict__ seq_dst,
                            const int* __restrict__ assign_src,
                            const int* __restrict__ assign_dst,
                            const float* __restrict__ polarity,
                            const float4* __restrict__ x_terrain4,
                            const float* __restrict__ W_seq,
                            float4* __restrict__ out_t4,
                            int e_seq) {
    int t = blockIdx.x * blockDim.x + threadIdx.x;
    int e0 = 4 * t;
    if (e0 >= e_seq) return;

    float w[16];
#pragma unroll
    for (int j = 0; j < 16; ++j) w[j] = __ldg(&W_seq[j]);

    if (e0 + 3 < e_seq) {
        int4   s4 = __ldg((const int4*)(seq_src) + t);
        int4   d4 = __ldg((const int4*)(seq_dst) + t);
        int4   a4 = __ldg((const int4*)(assign_src) + t);
        int4   o4 = __ldg((const int4*)(assign_dst) + t);
        float4 p4 = __ldg((const float4*)(polarity) + t);
        int ss[4] = {s4.x, s4.y, s4.z, s4.w};
        int dd[4] = {d4.x, d4.y, d4.z, d4.w};
        int aa[4] = {a4.x, a4.y, a4.z, a4.w};
        int oo[4] = {o4.x, o4.y, o4.z, o4.w};
        float pp[4] = {p4.x, p4.y, p4.z, p4.w};
#pragma unroll
        for (int k = 0; k < 4; ++k) {
            unsigned long long op = (unsigned long long)(max(0, min(oo[k], 3)));
            unsigned long long packed = ((unsigned long long)(e0 + k) << 34)
                                      | (op << 32)
                                      | (unsigned long long)__float_as_uint(pp[k]);
            atomicMin(&g_first[aa[k]], packed);

            float4 x = __ldg(&x_terrain4[ss[k]]);
            float m0 = w[0]  * x.x + w[1]  * x.y + w[2]  * x.z + w[3]  * x.w;
            float m1 = w[4]  * x.x + w[5]  * x.y + w[6]  * x.z + w[7]  * x.w;
            float m2 = w[8]  * x.x + w[9]  * x.y + w[10] * x.z + w[11] * x.w;
            float m3 = w[12] * x.x + w[13] * x.y + w[14] * x.z + w[15] * x.w;
            float4* dst = &out_t4[dd[k]];
            asm volatile("red.global.add.v4.f32 [%0], {%1, %2, %3, %4};"
                         :: "l"(dst), "f"(m0), "f"(m1), "f"(m2), "f"(m3) : "memory");
        }
    } else {
        for (int e = e0; e < e_seq; ++e) {
            int s = seq_src[e];
            int d = seq_dst[e];
            int a = assign_src[e];
            unsigned long long op = (unsigned long long)(max(0, min(assign_dst[e], 3)));
            unsigned long long packed = ((unsigned long long)e << 34)
                                      | (op << 32)
                                      | (unsigned long long)__float_as_uint(polarity[e]);
            atomicMin(&g_first[a], packed);

            float4 x = __ldg(&x_terrain4[s]);
            float m0 = w[0]  * x.x + w[1]  * x.y + w[2]  * x.z + w[3]  * x.w;
            float m1 = w[4]  * x.x + w[5]  * x.y + w[6]  * x.z + w[7]  * x.w;
            float m2 = w[8]  * x.x + w[9]  * x.y + w[10] * x.z + w[11] * x.w;
            float m3 = w[12] * x.x + w[13] * x.y + w[14] * x.z + w[15] * x.w;
            float4* dst = &out_t4[d];
            asm volatile("red.global.add.v4.f32 [%0], {%1, %2, %3, %4};"
                         :: "l"(dst), "f"(m0), "f"(m1), "f"(m2), "f"(m3) : "memory");
        }
    }
}

// ---------------------------------------------------------------------------
// Stage 2b (s2, after seq): operator transform — fully coalesced.
// DRAM-bound; hides under transport's 92µs window on s0.
// ---------------------------------------------------------------------------
__global__ void k_op(float4* __restrict__ out_t4,
                     const float* __restrict__ op_W,
                     const float* __restrict__ op_b,
                     int n_t, int e_as) {
    int n = blockIdx.x * blockDim.x + threadIdx.x;
    if (n >= n_t) return;
    unsigned long long v = g_first[n];
    unsigned int f = (unsigned int)(v >> 34);
    if (f >= (unsigned int)e_as) return;

    int   op = (int)((v >> 32) & 3ull);
    float p  = __uint_as_float((unsigned int)(v & 0xffffffffull));

    float4 x = out_t4[n];
    const float* W = op_W + op * 20;   // [4][5] row-major
    const float* b = op_b + op * 4;

    float4 y;
    y.x = __ldg(&W[0])  * x.x + __ldg(&W[1])  * x.y + __ldg(&W[2])  * x.z + __ldg(&W[3])  * x.w + __ldg(&W[4])  * p + __ldg(&b[0]);
    y.y = __ldg(&W[5])  * x.x + __ldg(&W[6])  * x.y + __ldg(&W[7])  * x.z + __ldg(&W[8])  * x.w + __ldg(&W[9])  * p + __ldg(&b[1]);
    y.z = __ldg(&W[10]) * x.x + __ldg(&W[11]) * x.y + __ldg(&W[12]) * x.z + __ldg(&W[13]) * x.w + __ldg(&W[14]) * p + __ldg(&b[2]);
    y.w = __ldg(&W[15]) * x.x + __ldg(&W[16]) * x.y + __ldg(&W[17]) * x.z + __ldg(&W[18]) * x.w + __ldg(&W[19]) * p + __ldg(&b[3]);
    out_t4[n] = y;
}

// ---------------------------------------------------------------------------
// Stage 2c (s0): transport edges, 4 edges/thread.
// Scattered ops/edge: LDG.128 stage[src], LDG.32 stage[dst].w, RED.128 = 3.
// Runs at the L1tex wavefront ceiling (~1 wf/cyc/SM) — structural floor.
// ---------------------------------------------------------------------------
__global__ void k_transport(const int* __restrict__ tr_src,
                            const int* __restrict__ tr_dst,
                            const float* __restrict__ gate_W,
                            int e_tr) {
    int t = blockIdx.x * blockDim.x + threadIdx.x;
    int e0 = 4 * t;
    if (e0 >= e_tr) return;

    float w3 = __ldg(&gate_W[3]);
    float w4 = __ldg(&gate_W[4]);
    float w5 = __ldg(&gate_W[5]);
    const float* stage_f = (const float*)g_stage;

    if (e0 + 3 < e_tr) {
        int4 s4 = __ldg((const int4*)(tr_src) + t);
        int4 d4 = __ldg((const int4*)(tr_dst) + t);
        int ss[4] = {s4.x, s4.y, s4.z, s4.w};
        int dd[4] = {d4.x, d4.y, d4.z, d4.w};
#pragma unroll
        for (int k = 0; k < 4; ++k) {
            float4 v = __ldg(&g_stage[ss[k]]);
            float a  = __ldg(&stage_f[4 * dd[k] + 3]);
            float z  = a + w3 * v.x + w4 * v.y + w5 * v.z;
            float g  = 1.0f / (1.0f + __expf(-z));
            float4* dst = &g_sum[dd[k]];
            asm volatile("red.global.add.v4.f32 [%0], {%1, %2, %3, %4};"
                         :: "l"(dst), "f"(g * v.x), "f"(g * v.y), "f"(g * v.z), "f"(1.0f)
                         : "memory");
        }
    } else {
        for (int e = e0; e < e_tr; ++e) {
            int s = tr_src[e];
            int d = tr_dst[e];
            float4 v = __ldg(&g_stage[s]);
            float a  = __ldg(&stage_f[4 * d + 3]);
            float z  = a + w3 * v.x + w4 * v.y + w5 * v.z;
            float g  = 1.0f / (1.0f + __expf(-z));
            float4* dst = &g_sum[d];
            asm volatile("red.global.add.v4.f32 [%0], {%1, %2, %3, %4};"
                         :: "l"(dst), "f"(g * v.x), "f"(g * v.y), "f"(g * v.z), "f"(1.0f)
                         : "memory");
        }
    }
}

// ---------------------------------------------------------------------------
// Stage 3 (s0, pre-join): torus finalize. out = x + sum / max(count, 1)
// ---------------------------------------------------------------------------
__global__ void k_finalize(float* __restrict__ out_tor, int n_tor) {
    int n = blockIdx.x * blockDim.x + threadIdx.x;
    if (n >= n_tor) return;
    float4 sv = g_sum[n];
    float4 xv = g_stage[n];
    float inv = 1.0f / fmaxf(sv.w, 1.0f);
    out_tor[3 * n + 0] = xv.x + sv.x * inv;
    out_tor[3 * n + 1] = xv.y + sv.y * inv;
    out_tor[3 * n + 2] = xv.z + sv.z * inv;
}

extern "C" void kernel_launch(void* const* d_in, const int* in_sizes, int n_in,
                              void* d_out, int out_size) {
    const float* x_terrain  = (const float*)d_in[0];
    const float* polarity   = (const float*)d_in[1];
    const float* x_torus    = (const float*)d_in[2];
    const int*   seq_ei     = (const int*)d_in[3];
    const int*   assign_src = (const int*)d_in[4];
    const int*   assign_dst = (const int*)d_in[5];
    const int*   tr_ei      = (const int*)d_in[6];
    const float* W_seq      = (const float*)d_in[7];
    const float* op_W       = (const float*)d_in[8];
    const float* op_b       = (const float*)d_in[9];
    const float* gate_W     = (const float*)d_in[10];
    const float* gate_b     = (const float*)d_in[11];

    const int TD = 4, OD = 3;
    int n_t   = in_sizes[0] / TD;      // 2,000,000
    int e_as  = in_sizes[4];           // 2,000,000
    int n_tor = in_sizes[2] / OD;      // 1,000,000
    int e_seq = in_sizes[3] / 2;       // 2,000,000
    int e_tr  = in_sizes[6] / 2;       // 8,000,000

    float* out_t   = (float*)d_out;            // [n_t, 4]
    float* out_tor = out_t + (size_t)n_t * TD; // [n_tor, 3]

    // One-time side-stream + events for fork/join graph branches.
    static cudaStream_t s2 = nullptr;
    static cudaEvent_t evFork = nullptr, evJoin = nullptr;
    if (s2 == nullptr) {
        cudaStreamCreateWithFlags(&s2, cudaStreamNonBlocking);
        cudaEventCreateWithFlags(&evFork, cudaEventDisableTiming);
        cudaEventCreateWithFlags(&evJoin, cudaEventDisableTiming);
    }

    const int B = 256;

    // Stage 1: fused init, serial on origin stream (R8's verified prologue).
    k_init_all<<<(n_t + B - 1) / B, B>>>((const float4*)x_terrain, (float4*)out_t,
                                         x_torus, gate_W, gate_b, n_t, n_tor);

    // Fork after init: terrain tail (seq -> op) on s2; torus tail on s0.
    cudaEventRecord(evFork, 0);
    cudaStreamWaitEvent(s2, evFork, 0);

    int t_seq = (e_seq + 3) / 4;
    k_edges_seq<<<(t_seq + B - 1) / B, B, 0, s2>>>(
        seq_ei, seq_ei + e_seq, assign_src, assign_dst, polarity,
        (const float4*)x_terrain, W_seq, (float4*)out_t, e_seq);

    k_op<<<(n_t + B - 1) / B, B, 0, s2>>>(
        (float4*)out_t, op_W, op_b, n_t, e_as);

    cudaEventRecord(evJoin, s2);

    int t_tr = (e_tr + 3) / 4;
    k_transport<<<(t_tr + B - 1) / B, B>>>(tr_ei, tr_ei + e_tr, gate_W, e_tr);

    k_finalize<<<(n_tor + B - 1) / B, B>>>(out_tor, n_tor);

    // Join: everything complete when origin stream drains.
    cudaStreamWaitEvent(0, evJoin, 0);
}